// round 16
// baseline (speedup 1.0000x reference)
#include <cuda_runtime.h>
#include <cuda_fp16.h>
#include <cstdint>

// ============================================================================
// Problem constants
// ============================================================================
#define M_TOTAL 8192   // B*S = 4*2048
#define DIN     2048
#define DOUT    2048
#define QDIV    358.4f // 448 * 0.8

// GEMM tiling: fp8 bytes in SMEM (f16 MMA after in-register cvt).
// 128x128 CTA tile, K-chunk 128 fp8 per stage (32KB/stage), 3 stages,
// 256 threads, 2 CTAs/SM.
#define BM 128
#define BN 128
#define KCHUNK 128
#define STAGES 3
#define NIT (DIN / KCHUNK)   // 16 outer iterations, 8 k16-steps each

// Fused prologue: 888 CTAs (6/SM x 148 SMs; co-resident even at a
// conservative 1536 threads/SM) -> grid ticket barrier is deadlock-free.
#define PGRID 888

// ============================================================================
// Device-global scratch (allocation-free requirement)
// ============================================================================
__device__ float    g_px[PGRID];   // per-CTA |x| maxes (plain stores)
__device__ float    g_pw[PGRID];   // per-CTA |w| maxes
__device__ unsigned g_bar;         // monotonic ticket barrier counter
__device__ float    g_osc;         // sx*sw, published by prologue CTA 0
// raw e4m3 bytes, k-PERMUTED within each 16-k group:
// byte pos (0..15) -> orig k: 0,1,8,9, 2,3,10,11, 4,5,12,13, 6,7,14,15
// (so cvt of lo/hi halves of each ldmatrix b16 reg yields the exact
//  m16n8k16 fragment k-pairs)
__device__ __align__(128) uint8_t g_qx[(size_t)M_TOTAL * DIN];   // 16 MB
__device__ __align__(128) uint8_t g_qw[(size_t)DOUT * DIN];      //  4 MB

// ============================================================================
// Helpers
// ============================================================================
__device__ __forceinline__ uint32_t smem_to_u32(const void* p) {
    uint32_t a;
    asm("{ .reg .u64 t; cvta.to.shared.u64 t, %1; cvt.u32.u64 %0, t; }"
        : "=r"(a) : "l"(p));
    return a;
}

// fp32x2 -> packed e4m3x2 (RN, satfinite). low byte = lo, high byte = hi.
__device__ __forceinline__ uint32_t cvt_e4m3x2(float hi, float lo) {
    uint16_t r;
    asm("cvt.rn.satfinite.e4m3x2.f32 %0, %1, %2;" : "=h"(r) : "f"(hi), "f"(lo));
    return (uint32_t)r;
}

// one raw b16 reg (4 fp8) -> two f16x2 regs (lo pair, hi pair); exact.
__device__ __forceinline__ void cvt_pair(uint32_t src, uint32_t& lo,
                                         uint32_t& hi) {
    uint16_t l = (uint16_t)src;
    uint16_t h = (uint16_t)(src >> 16);
    asm("cvt.rn.f16x2.e4m3x2 %0, %1;" : "=r"(lo) : "h"(l));
    asm("cvt.rn.f16x2.e4m3x2 %0, %1;" : "=r"(hi) : "h"(h));
}

#define CP_ASYNC_16(dst, src) \
    asm volatile("cp.async.cg.shared.global [%0], [%1], 16;" \
                 :: "r"(dst), "l"(src))
#define CP_ASYNC_COMMIT() asm volatile("cp.async.commit_group;")
#define CP_ASYNC_WAIT_1() asm volatile("cp.async.wait_group 1;")

#define LDSM_X4(r, addr) \
    asm volatile("ldmatrix.sync.aligned.m8n8.x4.shared.b16 {%0,%1,%2,%3}, [%4];" \
        : "=r"((r)[0]), "=r"((r)[1]), "=r"((r)[2]), "=r"((r)[3]) : "r"(addr))

__device__ __forceinline__ void mma16816(float* d, const uint32_t* a,
                                         const uint32_t* b) {
    asm volatile(
        "mma.sync.aligned.m16n8k16.row.col.f32.f16.f16.f32 "
        "{%0,%1,%2,%3}, {%4,%5,%6,%7}, {%8,%9}, {%0,%1,%2,%3};"
        : "+f"(d[0]), "+f"(d[1]), "+f"(d[2]), "+f"(d[3])
        : "r"(a[0]), "r"(a[1]), "r"(a[2]), "r"(a[3]), "r"(b[0]), "r"(b[1]));
}

// SW128 swizzle for 128-byte rows (byte offsets)
__device__ __forceinline__ uint32_t swz(uint32_t off) {
    return off ^ ((off >> 3) & 0x70);
}

// div via reciprocal + one FMA residual refinement (== IEEE div for all but
// ~2^-40 of inputs; 3-mantissa-bit e4m3 RNE absorbs the rest)
__device__ __forceinline__ float div_cr(float x, float s, float inv) {
    float y = x * inv;
    float e = fmaf(-s, y, x);
    return fmaf(e, inv, y);
}

__device__ __forceinline__ float max4(float4 v) {
    return fmaxf(fmaxf(fabsf(v.x), fabsf(v.y)),
                 fmaxf(fabsf(v.z), fabsf(v.w)));
}

// block-level max reduction (256 threads), result valid in thread 0
__device__ __forceinline__ float block_max_256(float m, float* sred) {
    #pragma unroll
    for (int o = 16; o; o >>= 1)
        m = fmaxf(m, __shfl_xor_sync(0xFFFFFFFFu, m, o));
    if ((threadIdx.x & 31) == 0) sred[threadIdx.x >> 5] = m;
    __syncthreads();
    if (threadIdx.x < 8) {
        m = sred[threadIdx.x];
        #pragma unroll
        for (int o = 4; o; o >>= 1)
            m = fmaxf(m, __shfl_xor_sync(0xFFu, m, o));
    }
    return m;
}

// ============================================================================
// Kernel 1: fused amax + quant, one launch, grid ticket barrier.
// Low-reg, no big smem -> 6+ CTAs/SM co-resident at PGRID=888.
// ============================================================================
__global__ __launch_bounds__(256) void prologue_kernel(
    const float4* __restrict__ x, const float4* __restrict__ w)
{
    __shared__ float sred[8];
    __shared__ float s_ax, s_aw;
    const int tid = threadIdx.x;
    const int bid = blockIdx.x;

    // ---- Phase A: amax (MLP-4 chunked reads) ----
    {
        float m0 = 0.f, m1 = 0.f, m2 = 0.f, m3 = 0.f;
        for (int c = bid; c < 4096; c += PGRID) {   // x: 4096 x 1024 float4
            int i = c * 1024 + tid;
            float4 v0 = x[i];
            float4 v1 = x[i + 256];
            float4 v2 = x[i + 512];
            float4 v3 = x[i + 768];
            m0 = fmaxf(m0, max4(v0));
            m1 = fmaxf(m1, max4(v1));
            m2 = fmaxf(m2, max4(v2));
            m3 = fmaxf(m3, max4(v3));
        }
        float mx = fmaxf(fmaxf(m0, m1), fmaxf(m2, m3));
        m0 = m1 = m2 = m3 = 0.f;
        for (int c = bid; c < 1024; c += PGRID) {   // w: 1024 x 1024 float4
            int i = c * 1024 + tid;
            float4 v0 = w[i];
            float4 v1 = w[i + 256];
            float4 v2 = w[i + 512];
            float4 v3 = w[i + 768];
            m0 = fmaxf(m0, max4(v0));
            m1 = fmaxf(m1, max4(v1));
            m2 = fmaxf(m2, max4(v2));
            m3 = fmaxf(m3, max4(v3));
        }
        float mw = fmaxf(fmaxf(m0, m1), fmaxf(m2, m3));
        float rx = block_max_256(mx, sred);
        if (tid == 0) g_px[bid] = rx;
        __syncthreads();
        float rw = block_max_256(mw, sred);
        if (tid == 0) g_pw[bid] = rw;
    }

    // ---- grid ticket barrier (monotonic counter: graph-replay safe) ----
    __threadfence();
    __syncthreads();
    if (tid == 0) {
        unsigned t = atomicAdd(&g_bar, 1u);
        unsigned end = t - (t % PGRID) + PGRID;
        while (atomicAdd(&g_bar, 0u) < end) __nanosleep(64);
    }
    __syncthreads();

    // ---- reduce the 888 partials (every CTA, identical result) ----
    {
        float vx = g_px[tid], vw = g_pw[tid];
        vx = fmaxf(vx, g_px[tid + 256]);
        vw = fmaxf(vw, g_pw[tid + 256]);
        vx = fmaxf(vx, g_px[tid + 512]);
        vw = fmaxf(vw, g_pw[tid + 512]);
        if (tid < PGRID - 768) {
            vx = fmaxf(vx, g_px[tid + 768]);
            vw = fmaxf(vw, g_pw[tid + 768]);
        }
        float rx = block_max_256(vx, sred);
        if (tid == 0) s_ax = rx;
        __syncthreads();
        float rw = block_max_256(vw, sred);
        if (tid == 0) s_aw = rw;
        __syncthreads();
    }
    const float ax = s_ax, aw = s_aw;
    const float sx_ = ax / QDIV;
    const float sw_ = fmaxf(ax, aw) / QDIV;
    const float invx = 1.0f / sx_;
    const float invw = 1.0f / sw_;
    if (bid == 0 && tid == 0)
        g_osc = sx_ * sw_;   // consumed by the (stream-ordered) gemm launch

    // ---- Phase B: quant (reads hit warm L2 from Phase A) ----
    // x: raw e4m3, k-permuted; one 16-float group per thread-step.
    {
        uint4* q = (uint4*)g_qx;
        for (int g = bid * 256 + tid; g < (M_TOTAL * DIN) / 16;
             g += PGRID * 256) {
            float4 f0 = x[4 * g];       // k0..3
            float4 f1 = x[4 * g + 1];   // k4..7
            float4 f2 = x[4 * g + 2];   // k8..11
            float4 f3 = x[4 * g + 3];   // k12..15
            #define Q(v) div_cr(v, sx_, invx)
            uint4 o;
            o.x = cvt_e4m3x2(Q(f0.y), Q(f0.x)) | (cvt_e4m3x2(Q(f2.y), Q(f2.x)) << 16);
            o.y = cvt_e4m3x2(Q(f0.w), Q(f0.z)) | (cvt_e4m3x2(Q(f2.w), Q(f2.z)) << 16);
            o.z = cvt_e4m3x2(Q(f1.y), Q(f1.x)) | (cvt_e4m3x2(Q(f3.y), Q(f3.x)) << 16);
            o.w = cvt_e4m3x2(Q(f1.w), Q(f1.z)) | (cvt_e4m3x2(Q(f3.w), Q(f3.z)) << 16);
            #undef Q
            q[g] = o;
        }
    }
    {
        uint4* q = (uint4*)g_qw;
        for (int g = bid * 256 + tid; g < (DOUT * DIN) / 16;
             g += PGRID * 256) {
            float4 f0 = w[4 * g];
            float4 f1 = w[4 * g + 1];
            float4 f2 = w[4 * g + 2];
            float4 f3 = w[4 * g + 3];
            #define Q(v) div_cr(v, sw_, invw)
            uint4 o;
            o.x = cvt_e4m3x2(Q(f0.y), Q(f0.x)) | (cvt_e4m3x2(Q(f2.y), Q(f2.x)) << 16);
            o.y = cvt_e4m3x2(Q(f0.w), Q(f0.z)) | (cvt_e4m3x2(Q(f2.w), Q(f2.z)) << 16);
            o.z = cvt_e4m3x2(Q(f1.y), Q(f1.x)) | (cvt_e4m3x2(Q(f3.y), Q(f3.x)) << 16);
            o.w = cvt_e4m3x2(Q(f1.w), Q(f1.z)) | (cvt_e4m3x2(Q(f3.w), Q(f3.z)) << 16);
            #undef Q
            q[g] = o;
        }
    }
}

// ============================================================================
// Kernel 2: GEMM — fp8 in SMEM, in-register cvt to f16, HMMA m16n8k16.
// 128x128 CTA tile, K-chunk 128/stage, 3 stages, 2 CTAs/SM,
// 8 warps 2(M)x4(N), warp tile 64x32. (R13/R15 champion, unchanged.)
// ============================================================================
#define STAGE_BYTES 32768                 // A 16KB + B 16KB (fp8!)
#define GEMM_SMEM_BYTES (STAGES * STAGE_BYTES)   // 98304

__global__ __launch_bounds__(256, 2) void gemm_kernel(
    float* __restrict__ out, const float* __restrict__ bias)
{
    extern __shared__ char smem[];
    const uint32_t sb = smem_to_u32(smem);
    const int tid  = threadIdx.x;
    const int lane = tid & 31;
    const int warp = tid >> 5;
    const int wm = warp >> 2;       // 0..1
    const int wn = warp & 3;        // 0..3
    const int nt = blockIdx.x;      // 0..15
    const int mt = blockIdx.y;      // 0..63

    const char* gA = (const char*)g_qx + (size_t)mt * BM * DIN;
    const char* gB = (const char*)g_qw + (size_t)nt * BN * DIN;

    // ---- cp.async chunk map: 1024 16B chunks per tile, 4/thread ----
    uint32_t dstA[4], dstB[4];
    uint32_t rowoff[4];
    #pragma unroll
    for (int q = 0; q < 4; ++q) {
        int ch  = tid + q * 256;
        int row = ch >> 3;
        int cb  = (ch & 7) * 16;
        uint32_t sw = swz((uint32_t)(row * 128 + cb));
        dstA[q] = sw;
        dstB[q] = 16384u + sw;
        rowoff[q] = (uint32_t)(row * DIN + cb);
    }

    // ---- prologue: fill STAGES-1 stages ----
    int li = 0;
    #pragma unroll
    for (int s = 0; s < STAGES - 1; ++s) {
        uint32_t st = sb + s * STAGE_BYTES;
        #pragma unroll
        for (int q = 0; q < 4; ++q) {
            CP_ASYNC_16(st + dstA[q], gA + rowoff[q] + li * KCHUNK);
            CP_ASYNC_16(st + dstB[q], gB + rowoff[q] + li * KCHUNK);
        }
        CP_ASYNC_COMMIT();
        ++li;
    }
    CP_ASYNC_WAIT_1();
    __syncthreads();

    // ---- ldmatrix addressing ----
    const uint32_t xr = (uint32_t)((lane & 7) << 4);
    const uint32_t baseA0 = (uint32_t)((wm * 64 + ((lane >> 3) * 8) + (lane & 7)) * 128);
    const uint32_t baseA1 = baseA0 + 32 * 128;
    const uint32_t baseB  = (uint32_t)((wn * 32 + ((lane >> 3) * 8) + (lane & 7)) * 128);

    float acc[4][4][4];
    #pragma unroll
    for (int i = 0; i < 4; ++i)
        #pragma unroll
        for (int j = 0; j < 4; ++j)
            #pragma unroll
            for (int r = 0; r < 4; ++r) acc[i][j][r] = 0.0f;

    // raw fp8 fragments, double buffered across k-steps
    uint32_t ra[2][2][4];   // [buf][ldsm l][reg]
    uint32_t rb[2][4];      // [buf][reg]

    // ---- main loop: 16 chunks x 8 k16-steps ----
    #pragma unroll 1
    for (int it = 0; it < NIT; ++it) {
        const int cur = it % STAGES;
        const uint32_t stA = sb + cur * STAGE_BYTES;
        const uint32_t stB = stA + 16384;

        // k-step 0 raw preload (stage cur complete & synced)
        LDSM_X4(ra[0][0], stA + baseA0 + (0u ^ xr));
        LDSM_X4(ra[0][1], stA + baseA1 + (0u ^ xr));
        LDSM_X4(rb[0],    stB + baseB  + (0u ^ xr));

        // issue loads 2 chunks ahead
        if (li < NIT) {
            const int nx = (it + STAGES - 1) % STAGES;
            uint32_t st = sb + nx * STAGE_BYTES;
            #pragma unroll
            for (int q = 0; q < 4; ++q) {
                CP_ASYNC_16(st + dstA[q], gA + rowoff[q] + li * KCHUNK);
                CP_ASYNC_16(st + dstB[q], gB + rowoff[q] + li * KCHUNK);
            }
            ++li;
        }
        CP_ASYNC_COMMIT();

        // 8 k16-steps: prefetch raw s+1, cvt + MMA s
        #pragma unroll
        for (int s = 0; s < 8; ++s) {
            const int cb = s & 1, nb = cb ^ 1;
            if (s < 7) {
                const uint32_t col = (uint32_t)((s + 1) * 16) ^ xr;
                LDSM_X4(ra[nb][0], stA + baseA0 + col);
                LDSM_X4(ra[nb][1], stA + baseA1 + col);
                LDSM_X4(rb[nb],    stB + baseB  + col);
            }
            // cvt B: reg j -> (k-block0 pair, k-block1 pair)
            uint32_t bf[8];
            #pragma unroll
            for (int j = 0; j < 4; ++j)
                cvt_pair(rb[cb][j], bf[2 * j], bf[2 * j + 1]);
            // cvt A per i-block + MMAs
            #pragma unroll
            for (int l = 0; l < 2; ++l) {
                #pragma unroll
                for (int ii = 0; ii < 2; ++ii) {
                    uint32_t a[4];
                    cvt_pair(ra[cb][l][2 * ii],     a[0], a[2]);
                    cvt_pair(ra[cb][l][2 * ii + 1], a[1], a[3]);
                    const int i = 2 * l + ii;
                    #pragma unroll
                    for (int j = 0; j < 4; ++j)
                        mma16816(acc[i][j], a, bf + 2 * j);
                }
            }
        }

        CP_ASYNC_WAIT_1();
        __syncthreads();
    }

    // ---- epilogue: scale + bias ----
    const float osc = g_osc;
    const int m0 = mt * BM + wm * 64 + (lane >> 2);
    const int n0 = nt * BN + wn * 32 + (lane & 3) * 2;
    #pragma unroll
    for (int i = 0; i < 4; ++i) {
        #pragma unroll
        for (int j = 0; j < 4; ++j) {
            const int m = m0 + i * 16;
            const int n = n0 + j * 8;
            const float b0 = __ldg(&bias[n]);
            const float b1 = __ldg(&bias[n + 1]);
            float2 v0, v1;
            v0.x = fmaf(acc[i][j][0], osc, b0);
            v0.y = fmaf(acc[i][j][1], osc, b1);
            v1.x = fmaf(acc[i][j][2], osc, b0);
            v1.y = fmaf(acc[i][j][3], osc, b1);
            *(float2*)&out[(size_t)m * DOUT + n]       = v0;
            *(float2*)&out[(size_t)(m + 8) * DOUT + n] = v1;
        }
    }
}

// ============================================================================
// kernel_launch: 2 launches (fused prologue, gemm)
// ============================================================================
extern "C" void kernel_launch(void* const* d_in, const int* in_sizes, int n_in,
                              void* d_out, int out_size) {
    const float* x    = (const float*)d_in[0];   // [4,2048,2048]
    const float* w    = (const float*)d_in[1];   // [2048,2048]
    const float* bias = (const float*)d_in[2];   // [2048]
    float* out = (float*)d_out;

    static int smem_set = 0;
    if (!smem_set) {
        cudaFuncSetAttribute(gemm_kernel,
                             cudaFuncAttributeMaxDynamicSharedMemorySize,
                             GEMM_SMEM_BYTES);
        smem_set = 1;
    }

    prologue_kernel<<<PGRID, 256>>>((const float4*)x, (const float4*)w);

    dim3 grid(DOUT / BN, M_TOTAL / BM);  // (16, 64) = 1024 CTAs
    gemm_kernel<<<grid, 256, GEMM_SMEM_BYTES>>>(out, bias);
}

// round 17
// speedup vs baseline: 1.0225x; 1.0225x over previous
#include <cuda_runtime.h>
#include <cuda_fp16.h>
#include <cstdint>

// ============================================================================
// Problem constants
// ============================================================================
#define M_TOTAL 8192   // B*S = 4*2048
#define DIN     2048
#define DOUT    2048
#define QDIV    358.4f // 448 * 0.8

// GEMM tiling: fp8 bytes in SMEM (f16 MMA after in-register cvt).
// 128x128 CTA tile, K-chunk 128 fp8 per stage (32KB/stage), 3 stages,
// 256 threads, 2 CTAs/SM.
#define BM 128
#define BN 128
#define KCHUNK 128
#define STAGES 3
#define NIT (DIN / KCHUNK)   // 16 outer iterations, 8 k16-steps each

#define AMAX_XBLK 1024
#define AMAX_WBLK 512
#define QUANT_XBLK 4096
#define QUANT_WBLK 1024

// ============================================================================
// Device-global scratch (allocation-free requirement)
// ============================================================================
__device__ float g_px[AMAX_XBLK];   // per-block |x| maxes (plain stores)
__device__ float g_pw[AMAX_WBLK];   // per-block |w| maxes
__device__ float g_osc;             // sx*sw, published by quant block 0
// raw e4m3 bytes, k-PERMUTED within each 16-k group:
// byte pos (0..15) -> orig k: 0,1,8,9, 2,3,10,11, 4,5,12,13, 6,7,14,15
// (so cvt of lo/hi halves of each ldmatrix b16 reg yields the exact
//  m16n8k16 fragment k-pairs)
__device__ __align__(128) uint8_t g_qx[(size_t)M_TOTAL * DIN];   // 16 MB
__device__ __align__(128) uint8_t g_qw[(size_t)DOUT * DIN];      //  4 MB

// ============================================================================
// Helpers
// ============================================================================
__device__ __forceinline__ uint32_t smem_to_u32(const void* p) {
    uint32_t a;
    asm("{ .reg .u64 t; cvta.to.shared.u64 t, %1; cvt.u32.u64 %0, t; }"
        : "=r"(a) : "l"(p));
    return a;
}

// fp32x2 -> packed e4m3x2 (RN, satfinite). low byte = lo, high byte = hi.
__device__ __forceinline__ uint32_t cvt_e4m3x2(float hi, float lo) {
    uint16_t r;
    asm("cvt.rn.satfinite.e4m3x2.f32 %0, %1, %2;" : "=h"(r) : "f"(hi), "f"(lo));
    return (uint32_t)r;
}

// one raw b16 reg (4 fp8) -> two f16x2 regs (lo pair, hi pair); exact.
__device__ __forceinline__ void cvt_pair(uint32_t src, uint32_t& lo,
                                         uint32_t& hi) {
    uint16_t l = (uint16_t)src;
    uint16_t h = (uint16_t)(src >> 16);
    asm("cvt.rn.f16x2.e4m3x2 %0, %1;" : "=r"(lo) : "h"(l));
    asm("cvt.rn.f16x2.e4m3x2 %0, %1;" : "=r"(hi) : "h"(h));
}

#define CP_ASYNC_16(dst, src) \
    asm volatile("cp.async.cg.shared.global [%0], [%1], 16;" \
                 :: "r"(dst), "l"(src))
#define CP_ASYNC_COMMIT() asm volatile("cp.async.commit_group;")
#define CP_ASYNC_WAIT_1() asm volatile("cp.async.wait_group 1;")

#define LDSM_X4(r, addr) \
    asm volatile("ldmatrix.sync.aligned.m8n8.x4.shared.b16 {%0,%1,%2,%3}, [%4];" \
        : "=r"((r)[0]), "=r"((r)[1]), "=r"((r)[2]), "=r"((r)[3]) : "r"(addr))

__device__ __forceinline__ void mma16816(float* d, const uint32_t* a,
                                         const uint32_t* b) {
    asm volatile(
        "mma.sync.aligned.m16n8k16.row.col.f32.f16.f16.f32 "
        "{%0,%1,%2,%3}, {%4,%5,%6,%7}, {%8,%9}, {%0,%1,%2,%3};"
        : "+f"(d[0]), "+f"(d[1]), "+f"(d[2]), "+f"(d[3])
        : "r"(a[0]), "r"(a[1]), "r"(a[2]), "r"(a[3]), "r"(b[0]), "r"(b[1]));
}

// SW128 swizzle for 128-byte rows (byte offsets)
__device__ __forceinline__ uint32_t swz(uint32_t off) {
    return off ^ ((off >> 3) & 0x70);
}

// div via reciprocal + one FMA residual refinement (== IEEE div for all but
// ~2^-40 of inputs; 3-mantissa-bit e4m3 RNE absorbs the rest)
__device__ __forceinline__ float div_cr(float x, float s, float inv) {
    float y = x * inv;
    float e = fmaf(-s, y, x);
    return fmaf(e, inv, y);
}

__device__ __forceinline__ float max4(float4 v) {
    return fmaxf(fmaxf(fabsf(v.x), fabsf(v.y)),
                 fmaxf(fabsf(v.z), fabsf(v.w)));
}

// block-level max reduction (256 threads), result valid in thread 0
__device__ __forceinline__ float block_max_256(float m, float* sred) {
    #pragma unroll
    for (int o = 16; o; o >>= 1)
        m = fmaxf(m, __shfl_xor_sync(0xFFFFFFFFu, m, o));
    if ((threadIdx.x & 31) == 0) sred[threadIdx.x >> 5] = m;
    __syncthreads();
    if (threadIdx.x < 8) {
        m = sred[threadIdx.x];
        #pragma unroll
        for (int o = 4; o; o >>= 1)
            m = fmaxf(m, __shfl_xor_sync(0xFFu, m, o));
    }
    return m;
}

// ============================================================================
// Kernel 1: fused amax over x (blocks [0,1024)) and w (blocks [1024,1536)).
// ============================================================================
__global__ void amax_kernel(const float4* __restrict__ x,
                            const float4* __restrict__ w) {
    __shared__ float sred[8];
    const bool is_w = blockIdx.x >= AMAX_XBLK;
    const float4* p = is_w ? w : x;
    const int n4 = is_w ? (DOUT * DIN / 4) : (M_TOTAL * DIN / 4);
    const int nblk = is_w ? AMAX_WBLK : AMAX_XBLK;
    const int b0 = is_w ? AMAX_XBLK : 0;
    const int bid = blockIdx.x - b0;
    const int stride = nblk * 256 * 4;
    float m0 = 0.0f, m1 = 0.0f, m2 = 0.0f, m3 = 0.0f;
    for (int i = bid * 256 * 4 + threadIdx.x; i < n4; i += stride) {
        float4 v0 = p[i];
        float4 v1 = p[i + 256];
        float4 v2 = p[i + 512];
        float4 v3 = p[i + 768];
        m0 = fmaxf(m0, max4(v0));
        m1 = fmaxf(m1, max4(v1));
        m2 = fmaxf(m2, max4(v2));
        m3 = fmaxf(m3, max4(v3));
    }
    float m = fmaxf(fmaxf(m0, m1), fmaxf(m2, m3));
    m = block_max_256(m, sred);
    if (threadIdx.x == 0) {
        if (is_w) g_pw[bid] = m;
        else      g_px[bid] = m;
    }
}

// ============================================================================
// Kernel 2: fused quantize x (blocks [0,4096)) and w (blocks [4096,5120)).
// One 16-k group per thread (exact). Writes k-PERMUTED e4m3 bytes (uint4).
// Block 0 publishes g_osc.
// ============================================================================
__global__ void quant_kernel(const float4* __restrict__ x,
                             const float4* __restrict__ w) {
    __shared__ float sred[8];
    __shared__ float s_ax, s_aw;
    {
        float mx = 0.0f, mw = 0.0f;
        #pragma unroll
        for (int q = 0; q < 4; ++q)
            mx = fmaxf(mx, g_px[threadIdx.x + q * 256]);
        #pragma unroll
        for (int q = 0; q < 2; ++q)
            mw = fmaxf(mw, g_pw[threadIdx.x + q * 256]);
        float rx = block_max_256(mx, sred);
        if (threadIdx.x == 0) s_ax = rx;
        __syncthreads();
        float rw = block_max_256(mw, sred);
        if (threadIdx.x == 0) s_aw = rw;
        __syncthreads();
    }
    const float ax = s_ax, aw = s_aw;
    if (blockIdx.x == 0 && threadIdx.x == 0)
        g_osc = (ax / QDIV) * (fmaxf(ax, aw) / QDIV);

    const bool is_w = blockIdx.x >= QUANT_XBLK;
    const float s   = is_w ? (fmaxf(ax, aw) / QDIV) : (ax / QDIV);
    const float inv = 1.0f / s;
    const float4* p = is_w ? w : x;
    uint4* q = (uint4*)(is_w ? (void*)g_qw : (void*)g_qx);
    const int b0 = is_w ? QUANT_XBLK : 0;
    // group g covers floats [16g, 16g+16); one group per thread, exact.
    const int g = (blockIdx.x - b0) * 256 + threadIdx.x;
    float4 f0 = p[4 * g];       // k0..3
    float4 f1 = p[4 * g + 1];   // k4..7
    float4 f2 = p[4 * g + 2];   // k8..11
    float4 f3 = p[4 * g + 3];   // k12..15
    #define Q(v) div_cr(v, s, inv)
    uint4 o;
    // pos pairs: (k0,k1)(k8,k9) | (k2,k3)(k10,k11) | (k4,k5)(k12,k13) | (k6,k7)(k14,k15)
    o.x = cvt_e4m3x2(Q(f0.y), Q(f0.x)) | (cvt_e4m3x2(Q(f2.y), Q(f2.x)) << 16);
    o.y = cvt_e4m3x2(Q(f0.w), Q(f0.z)) | (cvt_e4m3x2(Q(f2.w), Q(f2.z)) << 16);
    o.z = cvt_e4m3x2(Q(f1.y), Q(f1.x)) | (cvt_e4m3x2(Q(f3.y), Q(f3.x)) << 16);
    o.w = cvt_e4m3x2(Q(f1.w), Q(f1.z)) | (cvt_e4m3x2(Q(f3.w), Q(f3.z)) << 16);
    #undef Q
    q[g] = o;
}

// ============================================================================
// Kernel 3: GEMM — fp8 in SMEM, in-register cvt to f16, HMMA m16n8k16.
// 128x128 CTA tile, K-chunk 128/stage, 3 stages, 2 CTAs/SM,
// 8 warps 2(M)x4(N), warp tile 64x32.
// Outer loop unrolled x3 so stage indices are compile-time constants.
// ============================================================================
#define STAGE_BYTES 32768                 // A 16KB + B 16KB (fp8!)
#define GEMM_SMEM_BYTES (STAGES * STAGE_BYTES)   // 98304

__global__ __launch_bounds__(256, 2) void gemm_kernel(
    float* __restrict__ out, const float* __restrict__ bias)
{
    extern __shared__ char smem[];
    const uint32_t sb = smem_to_u32(smem);
    const int tid  = threadIdx.x;
    const int lane = tid & 31;
    const int warp = tid >> 5;
    const int wm = warp >> 2;       // 0..1
    const int wn = warp & 3;        // 0..3
    const int nt = blockIdx.x;      // 0..15
    const int mt = blockIdx.y;      // 0..63

    const char* gA = (const char*)g_qx + (size_t)mt * BM * DIN;
    const char* gB = (const char*)g_qw + (size_t)nt * BN * DIN;

    // ---- cp.async chunk map: 1024 16B chunks per tile, 4/thread ----
    uint32_t dstA[4], dstB[4];
    uint32_t rowoff[4];
    #pragma unroll
    for (int q = 0; q < 4; ++q) {
        int ch  = tid + q * 256;
        int row = ch >> 3;
        int cb  = (ch & 7) * 16;
        uint32_t sw = swz((uint32_t)(row * 128 + cb));
        dstA[q] = sw;
        dstB[q] = 16384u + sw;
        rowoff[q] = (uint32_t)(row * DIN + cb);
    }

    // ---- prologue: fill STAGES-1 stages ----
    int li = 0;
    #pragma unroll
    for (int s = 0; s < STAGES - 1; ++s) {
        uint32_t st = sb + s * STAGE_BYTES;
        #pragma unroll
        for (int q = 0; q < 4; ++q) {
            CP_ASYNC_16(st + dstA[q], gA + rowoff[q] + li * KCHUNK);
            CP_ASYNC_16(st + dstB[q], gB + rowoff[q] + li * KCHUNK);
        }
        CP_ASYNC_COMMIT();
        ++li;
    }
    CP_ASYNC_WAIT_1();
    __syncthreads();

    // ---- ldmatrix addressing ----
    const uint32_t xr = (uint32_t)((lane & 7) << 4);
    const uint32_t baseA0 = (uint32_t)((wm * 64 + ((lane >> 3) * 8) + (lane & 7)) * 128);
    const uint32_t baseA1 = baseA0 + 32 * 128;
    const uint32_t baseB  = (uint32_t)((wn * 32 + ((lane >> 3) * 8) + (lane & 7)) * 128);

    float acc[4][4][4];
    #pragma unroll
    for (int i = 0; i < 4; ++i)
        #pragma unroll
        for (int j = 0; j < 4; ++j)
            #pragma unroll
            for (int r = 0; r < 4; ++r) acc[i][j][r] = 0.0f;

    // raw fp8 fragments, double buffered across k-steps
    uint32_t ra[2][2][4];   // [buf][ldsm l][reg]
    uint32_t rb[2][4];      // [buf][reg]

    // ---- main loop: 16 chunks x 8 k16-steps; unroll x3 -> constant stages ----
    #pragma unroll 3
    for (int it = 0; it < NIT; ++it) {
        const int cur = it % STAGES;
        const uint32_t stA = sb + cur * STAGE_BYTES;
        const uint32_t stB = stA + 16384;

        // k-step 0 raw preload (stage cur complete & synced)
        LDSM_X4(ra[0][0], stA + baseA0 + (0u ^ xr));
        LDSM_X4(ra[0][1], stA + baseA1 + (0u ^ xr));
        LDSM_X4(rb[0],    stB + baseB  + (0u ^ xr));

        // issue loads 2 chunks ahead
        if (li < NIT) {
            const int nx = (it + STAGES - 1) % STAGES;
            uint32_t st = sb + nx * STAGE_BYTES;
            #pragma unroll
            for (int q = 0; q < 4; ++q) {
                CP_ASYNC_16(st + dstA[q], gA + rowoff[q] + li * KCHUNK);
                CP_ASYNC_16(st + dstB[q], gB + rowoff[q] + li * KCHUNK);
            }
            ++li;
        }
        CP_ASYNC_COMMIT();

        // 8 k16-steps: prefetch raw s+1, cvt + MMA s
        #pragma unroll
        for (int s = 0; s < 8; ++s) {
            const int cb = s & 1, nb = cb ^ 1;
            if (s < 7) {
                const uint32_t col = (uint32_t)((s + 1) * 16) ^ xr;
                LDSM_X4(ra[nb][0], stA + baseA0 + col);
                LDSM_X4(ra[nb][1], stA + baseA1 + col);
                LDSM_X4(rb[nb],    stB + baseB  + col);
            }
            // cvt B: reg j -> (k-block0 pair, k-block1 pair)
            uint32_t bf[8];
            #pragma unroll
            for (int j = 0; j < 4; ++j)
                cvt_pair(rb[cb][j], bf[2 * j], bf[2 * j + 1]);
            // cvt A per i-block + MMAs
            #pragma unroll
            for (int l = 0; l < 2; ++l) {
                #pragma unroll
                for (int ii = 0; ii < 2; ++ii) {
                    uint32_t a[4];
                    cvt_pair(ra[cb][l][2 * ii],     a[0], a[2]);
                    cvt_pair(ra[cb][l][2 * ii + 1], a[1], a[3]);
                    const int i = 2 * l + ii;
                    #pragma unroll
                    for (int j = 0; j < 4; ++j)
                        mma16816(acc[i][j], a, bf + 2 * j);
                }
            }
        }

        CP_ASYNC_WAIT_1();
        __syncthreads();
    }

    // ---- epilogue: scale + bias ----
    const float osc = g_osc;
    const int m0 = mt * BM + wm * 64 + (lane >> 2);
    const int n0 = nt * BN + wn * 32 + (lane & 3) * 2;
    #pragma unroll
    for (int i = 0; i < 4; ++i) {
        #pragma unroll
        for (int j = 0; j < 4; ++j) {
            const int m = m0 + i * 16;
            const int n = n0 + j * 8;
            const float b0 = __ldg(&bias[n]);
            const float b1 = __ldg(&bias[n + 1]);
            float2 v0, v1;
            v0.x = fmaf(acc[i][j][0], osc, b0);
            v0.y = fmaf(acc[i][j][1], osc, b1);
            v1.x = fmaf(acc[i][j][2], osc, b0);
            v1.y = fmaf(acc[i][j][3], osc, b1);
            *(float2*)&out[(size_t)m * DOUT + n]       = v0;
            *(float2*)&out[(size_t)(m + 8) * DOUT + n] = v1;
        }
    }
}

// ============================================================================
// kernel_launch: 3 launches (amax, quant, gemm)
// ============================================================================
extern "C" void kernel_launch(void* const* d_in, const int* in_sizes, int n_in,
                              void* d_out, int out_size) {
    const float* x    = (const float*)d_in[0];   // [4,2048,2048]
    const float* w    = (const float*)d_in[1];   // [2048,2048]
    const float* bias = (const float*)d_in[2];   // [2048]
    float* out = (float*)d_out;

    static int smem_set = 0;
    if (!smem_set) {
        cudaFuncSetAttribute(gemm_kernel,
                             cudaFuncAttributeMaxDynamicSharedMemorySize,
                             GEMM_SMEM_BYTES);
        smem_set = 1;
    }

    amax_kernel<<<AMAX_XBLK + AMAX_WBLK, 256>>>((const float4*)x,
                                                (const float4*)w);
    quant_kernel<<<QUANT_XBLK + QUANT_WBLK, 256>>>((const float4*)x,
                                                   (const float4*)w);

    dim3 grid(DOUT / BN, M_TOTAL / BM);  // (16, 64) = 1024 CTAs
    gemm_kernel<<<grid, 256, GEMM_SMEM_BYTES>>>(out, bias);
}